// round 1
// baseline (speedup 1.0000x reference)
#include <cuda_runtime.h>
#include <math.h>

#define HIDDEN 2048
#define HEADS 16
#define HD 128
#define SEQL 2048
#define NBATCH 2
#define MROWS (NBATCH * SEQL) // 4096

// Scratch: __device__ globals (no cudaMalloc allowed)
__device__ float g_q[(size_t)MROWS * HIDDEN];
__device__ float g_k[(size_t)MROWS * HIDDEN];
__device__ float g_v[(size_t)MROWS * HIDDEN];
__device__ float g_o[(size_t)MROWS * HIDDEN];

// ---------------------------------------------------------------------------
// C[M,N] = A[M,K] @ B[N,K]^T   (both operands K-contiguous)
// 128x128 tile, BK=8, 256 threads, 8x8 per thread (4+4 split for coalescing)
// ---------------------------------------------------------------------------
__global__ __launch_bounds__(256) void sgemm_nt(
    const float* __restrict__ A, const float* __restrict__ B,
    float* __restrict__ C, int M, int N, int K)
{
    __shared__ float As[8 * 128];
    __shared__ float Bs[8 * 128];
    const int tid = threadIdx.x;
    const int bm = blockIdx.y * 128, bn = blockIdx.x * 128;
    const int lr = tid >> 1;            // 0..127
    const int lc = (tid & 1) * 4;       // 0 or 4
    const int ty = tid >> 4, tx = tid & 15;

    float acc[8][8];
#pragma unroll
    for (int i = 0; i < 8; i++)
#pragma unroll
        for (int j = 0; j < 8; j++) acc[i][j] = 0.f;

    const float* Aptr = A + (size_t)(bm + lr) * K + lc;
    const float* Bptr = B + (size_t)(bn + lr) * K + lc;

    for (int k0 = 0; k0 < K; k0 += 8) {
        float4 a4 = *(const float4*)(Aptr + k0);
        float4 b4 = *(const float4*)(Bptr + k0);
        __syncthreads();
        As[(lc + 0) * 128 + lr] = a4.x;
        As[(lc + 1) * 128 + lr] = a4.y;
        As[(lc + 2) * 128 + lr] = a4.z;
        As[(lc + 3) * 128 + lr] = a4.w;
        Bs[(lc + 0) * 128 + lr] = b4.x;
        Bs[(lc + 1) * 128 + lr] = b4.y;
        Bs[(lc + 2) * 128 + lr] = b4.z;
        Bs[(lc + 3) * 128 + lr] = b4.w;
        __syncthreads();
#pragma unroll
        for (int kk = 0; kk < 8; kk++) {
            float4 ra0 = *(const float4*)&As[kk * 128 + ty * 4];
            float4 ra1 = *(const float4*)&As[kk * 128 + 64 + ty * 4];
            float4 rb0 = *(const float4*)&Bs[kk * 128 + tx * 4];
            float4 rb1 = *(const float4*)&Bs[kk * 128 + 64 + tx * 4];
            float ra[8] = {ra0.x, ra0.y, ra0.z, ra0.w, ra1.x, ra1.y, ra1.z, ra1.w};
            float rb[8] = {rb0.x, rb0.y, rb0.z, rb0.w, rb1.x, rb1.y, rb1.z, rb1.w};
#pragma unroll
            for (int i = 0; i < 8; i++)
#pragma unroll
                for (int j = 0; j < 8; j++)
                    acc[i][j] += ra[i] * rb[j];
        }
    }
#pragma unroll
    for (int i = 0; i < 8; i++) {
        int r = bm + ((i < 4) ? (ty * 4 + i) : (64 + ty * 4 + i - 4));
        float4 o0 = make_float4(acc[i][0], acc[i][1], acc[i][2], acc[i][3]);
        float4 o1 = make_float4(acc[i][4], acc[i][5], acc[i][6], acc[i][7]);
        *(float4*)&C[(size_t)r * N + bn + tx * 4] = o0;
        *(float4*)&C[(size_t)r * N + bn + 64 + tx * 4] = o1;
    }
}

// ---------------------------------------------------------------------------
// RoPE applied in-place to Q and K. One thread per (row, head, pair).
// ---------------------------------------------------------------------------
__global__ void rope_kernel(float* __restrict__ q, float* __restrict__ k)
{
    int idx = blockIdx.x * blockDim.x + threadIdx.x;
    // total = MROWS * HEADS * 64
    int d = idx & 63;
    int h = (idx >> 6) & (HEADS - 1);
    int m = idx >> 10;
    int l = m & (SEQL - 1);

    float e = (2.0f * (float)d) / 128.0f;
    float inv = 1.0f / powf(10000.0f, e);
    float ang = (float)l * inv;
    float s, c;
    sincosf(ang, &s, &c);

    size_t base = (size_t)m * HIDDEN + h * HD + d;
    float q1 = q[base], q2 = q[base + 64];
    q[base]      = q1 * c - q2 * s;
    q[base + 64] = q2 * c + q1 * s;
    float k1 = k[base], k2 = k[base + 64];
    k[base]      = k1 * c - k2 * s;
    k[base + 64] = k2 * c + k1 * s;
}

// ---------------------------------------------------------------------------
// Flash attention (causal), fp32. Grid: (qtile=32, head=16, batch=2).
// 64-row Q tile, 64-row K/V tiles, 256 threads (16x16), online softmax.
// ---------------------------------------------------------------------------
#define LDT 129
#define LDP 65

__global__ __launch_bounds__(256) void flash_kernel(
    const float* __restrict__ Q, const float* __restrict__ K,
    const float* __restrict__ V, float* __restrict__ O)
{
    extern __shared__ float sm[];
    float* Qs = sm;                   // [64][129]
    float* Ks = Qs + 64 * LDT;        // [64][129]
    float* Vs = Ks + 64 * LDT;        // [64][129]
    float* Ps = Vs + 64 * LDT;        // [64][65]

    const int qt = blockIdx.x, h = blockIdx.y, b = blockIdx.z;
    const int tid = threadIdx.x;
    const int ty = tid >> 4, tx = tid & 15;
    const float scale = 0.0883883476483184f; // 1/sqrt(128)

    // Load Q tile (64x128)
    for (int i = tid; i < 64 * 32; i += 256) {
        int r = i >> 5, c4 = (i & 31) << 2;
        float4 v4 = *(const float4*)&Q[(size_t)(b * SEQL + qt * 64 + r) * HIDDEN + h * HD + c4];
        Qs[r * LDT + c4 + 0] = v4.x;
        Qs[r * LDT + c4 + 1] = v4.y;
        Qs[r * LDT + c4 + 2] = v4.z;
        Qs[r * LDT + c4 + 3] = v4.w;
    }

    float m_i[4], l_i[4], acc[4][8];
#pragma unroll
    for (int i = 0; i < 4; i++) {
        m_i[i] = -INFINITY;
        l_i[i] = 0.f;
#pragma unroll
        for (int j = 0; j < 8; j++) acc[i][j] = 0.f;
    }

    for (int kt = 0; kt <= qt; kt++) {
        __syncthreads();
        // Load K, V tiles
        for (int i = tid; i < 64 * 32; i += 256) {
            int r = i >> 5, c4 = (i & 31) << 2;
            size_t g = (size_t)(b * SEQL + kt * 64 + r) * HIDDEN + h * HD + c4;
            float4 kv = *(const float4*)&K[g];
            float4 vv = *(const float4*)&V[g];
            Ks[r * LDT + c4 + 0] = kv.x;
            Ks[r * LDT + c4 + 1] = kv.y;
            Ks[r * LDT + c4 + 2] = kv.z;
            Ks[r * LDT + c4 + 3] = kv.w;
            Vs[r * LDT + c4 + 0] = vv.x;
            Vs[r * LDT + c4 + 1] = vv.y;
            Vs[r * LDT + c4 + 2] = vv.z;
            Vs[r * LDT + c4 + 3] = vv.w;
        }
        __syncthreads();

        // S = Q K^T (4x4 per thread)
        float s[4][4];
#pragma unroll
        for (int i = 0; i < 4; i++)
#pragma unroll
            for (int j = 0; j < 4; j++) s[i][j] = 0.f;

        for (int kk = 0; kk < HD; kk++) {
            float qa[4], kb[4];
#pragma unroll
            for (int i = 0; i < 4; i++) qa[i] = Qs[(ty * 4 + i) * LDT + kk];
#pragma unroll
            for (int j = 0; j < 4; j++) kb[j] = Ks[(tx * 4 + j) * LDT + kk];
#pragma unroll
            for (int i = 0; i < 4; i++)
#pragma unroll
                for (int j = 0; j < 4; j++)
                    s[i][j] += qa[i] * kb[j];
        }

        const bool diag = (kt == qt);
        float mt[4];
#pragma unroll
        for (int i = 0; i < 4; i++) {
#pragma unroll
            for (int j = 0; j < 4; j++) {
                s[i][j] *= scale;
                if (diag && (tx * 4 + j) > (ty * 4 + i)) s[i][j] = -INFINITY;
            }
            float mm = fmaxf(fmaxf(s[i][0], s[i][1]), fmaxf(s[i][2], s[i][3]));
#pragma unroll
            for (int msk = 1; msk <= 8; msk <<= 1)
                mm = fmaxf(mm, __shfl_xor_sync(0xffffffffu, mm, msk));
            mt[i] = mm;
        }

#pragma unroll
        for (int i = 0; i < 4; i++) {
            float mnew = fmaxf(m_i[i], mt[i]);
            float alpha = expf(m_i[i] - mnew);
            m_i[i] = mnew;
            float ps = 0.f;
#pragma unroll
            for (int j = 0; j < 4; j++) {
                float p = expf(s[i][j] - mnew);
                s[i][j] = p;
                ps += p;
            }
#pragma unroll
            for (int msk = 1; msk <= 8; msk <<= 1)
                ps += __shfl_xor_sync(0xffffffffu, ps, msk);
            l_i[i] = alpha * l_i[i] + ps;
#pragma unroll
            for (int j = 0; j < 8; j++) acc[i][j] *= alpha;
        }

        // Stage P through smem
#pragma unroll
        for (int i = 0; i < 4; i++)
#pragma unroll
            for (int j = 0; j < 4; j++)
                Ps[(ty * 4 + i) * LDP + tx * 4 + j] = s[i][j];
        __syncthreads();

        // O += P V  (4 rows x 8 cols per thread, 4+4 column split)
        for (int j = 0; j < 64; j++) {
            float pv[4];
#pragma unroll
            for (int i = 0; i < 4; i++) pv[i] = Ps[(ty * 4 + i) * LDP + j];
            float va[8];
#pragma unroll
            for (int c = 0; c < 4; c++) {
                va[c]     = Vs[j * LDT + tx * 4 + c];
                va[4 + c] = Vs[j * LDT + 64 + tx * 4 + c];
            }
#pragma unroll
            for (int i = 0; i < 4; i++)
#pragma unroll
                for (int c = 0; c < 8; c++)
                    acc[i][c] += pv[i] * va[c];
        }
    }

    // Epilogue: normalize and store
#pragma unroll
    for (int i = 0; i < 4; i++) {
        float inv = 1.0f / l_i[i];
        int r = qt * 64 + ty * 4 + i;
        size_t base = (size_t)(b * SEQL + r) * HIDDEN + h * HD;
#pragma unroll
        for (int c = 0; c < 4; c++) {
            O[base + tx * 4 + c]      = acc[i][c] * inv;
            O[base + 64 + tx * 4 + c] = acc[i][4 + c] * inv;
        }
    }
}

// ---------------------------------------------------------------------------
extern "C" void kernel_launch(void* const* d_in, const int* in_sizes, int n_in,
                              void* d_out, int out_size)
{
    const float* x  = (const float*)d_in[0];
    const float* wq = (const float*)d_in[1];
    const float* wk = (const float*)d_in[2];
    const float* wv = (const float*)d_in[3];
    const float* wo = (const float*)d_in[4];
    float* out = (float*)d_out;

    float *q, *k, *v, *o;
    cudaGetSymbolAddress((void**)&q, g_q);
    cudaGetSymbolAddress((void**)&k, g_k);
    cudaGetSymbolAddress((void**)&v, g_v);
    cudaGetSymbolAddress((void**)&o, g_o);

    dim3 gg(HIDDEN / 128, MROWS / 128);
    sgemm_nt<<<gg, 256>>>(x, wq, q, MROWS, HIDDEN, HIDDEN);
    sgemm_nt<<<gg, 256>>>(x, wk, k, MROWS, HIDDEN, HIDDEN);
    sgemm_nt<<<gg, 256>>>(x, wv, v, MROWS, HIDDEN, HIDDEN);

    rope_kernel<<<(MROWS * HEADS * 64) / 256, 256>>>(q, k);

    int smem = (3 * 64 * LDT + 64 * LDP) * (int)sizeof(float);
    cudaFuncSetAttribute(flash_kernel, cudaFuncAttributeMaxDynamicSharedMemorySize, smem);
    flash_kernel<<<dim3(SEQL / 64, HEADS, NBATCH), 256, smem>>>(q, k, v, o);

    sgemm_nt<<<gg, 256>>>(o, wo, out, MROWS, HIDDEN, HIDDEN);
}

// round 3
// speedup vs baseline: 1.3609x; 1.3609x over previous
#include <cuda_runtime.h>
#include <cuda_bf16.h>
#include <math.h>
#include <stdint.h>

#define HIDDEN 2048
#define HEADS 16
#define HD 128
#define SEQL 2048
#define NBATCH 2
#define MROWS (NBATCH * SEQL) // 4096
#define KDIM 2048

// ---------------------------------------------------------------------------
// Scratch: __device__ globals (no cudaMalloc allowed)
// ---------------------------------------------------------------------------
__device__ float g_q[(size_t)MROWS * HIDDEN];
__device__ float g_k[(size_t)MROWS * HIDDEN];
__device__ float g_v[(size_t)MROWS * HIDDEN];
__device__ float g_o[(size_t)MROWS * HIDDEN];

__device__ __nv_bfloat16 g_xh[(size_t)MROWS * HIDDEN];
__device__ __nv_bfloat16 g_xl[(size_t)MROWS * HIDDEN];
__device__ __nv_bfloat16 g_oh[(size_t)MROWS * HIDDEN];
__device__ __nv_bfloat16 g_ol[(size_t)MROWS * HIDDEN];
__device__ __nv_bfloat16 g_wqh[(size_t)HIDDEN * HIDDEN];
__device__ __nv_bfloat16 g_wql[(size_t)HIDDEN * HIDDEN];
__device__ __nv_bfloat16 g_wkh[(size_t)HIDDEN * HIDDEN];
__device__ __nv_bfloat16 g_wkl[(size_t)HIDDEN * HIDDEN];
__device__ __nv_bfloat16 g_wvh[(size_t)HIDDEN * HIDDEN];
__device__ __nv_bfloat16 g_wvl[(size_t)HIDDEN * HIDDEN];
__device__ __nv_bfloat16 g_woh[(size_t)HIDDEN * HIDDEN];
__device__ __nv_bfloat16 g_wol[(size_t)HIDDEN * HIDDEN];

// ---------------------------------------------------------------------------
// Split fp32 -> (bf16 hi, bf16 lo) elementwise, vectorized x4
// ---------------------------------------------------------------------------
__global__ void split_kernel(const float4* __restrict__ a,
                             __nv_bfloat16* __restrict__ hi,
                             __nv_bfloat16* __restrict__ lo, int n4)
{
    int i = blockIdx.x * blockDim.x + threadIdx.x;
    if (i >= n4) return;
    float4 v = a[i];
    __nv_bfloat16 h0 = __float2bfloat16(v.x);
    __nv_bfloat16 h1 = __float2bfloat16(v.y);
    __nv_bfloat16 h2 = __float2bfloat16(v.z);
    __nv_bfloat16 h3 = __float2bfloat16(v.w);
    __nv_bfloat16 l0 = __float2bfloat16(v.x - __bfloat162float(h0));
    __nv_bfloat16 l1 = __float2bfloat16(v.y - __bfloat162float(h1));
    __nv_bfloat16 l2 = __float2bfloat16(v.z - __bfloat162float(h2));
    __nv_bfloat16 l3 = __float2bfloat16(v.w - __bfloat162float(h3));
    ushort4 hv, lv;
    hv.x = __bfloat16_as_ushort(h0); hv.y = __bfloat16_as_ushort(h1);
    hv.z = __bfloat16_as_ushort(h2); hv.w = __bfloat16_as_ushort(h3);
    lv.x = __bfloat16_as_ushort(l0); lv.y = __bfloat16_as_ushort(l1);
    lv.z = __bfloat16_as_ushort(l2); lv.w = __bfloat16_as_ushort(l3);
    *(ushort4*)(hi + (size_t)i * 4) = hv;
    *(ushort4*)(lo + (size_t)i * 4) = lv;
}

// ---------------------------------------------------------------------------
// bf16x3 GEMM via mma.sync.m16n8k16:
//   C[4096,2048] fp32 = Ah@Bh^T + Ah@Bl^T + Al@Bh^T
// BM=128 BN=128 BK=32, 256 thr (8 warps, 4x2), warp tile 32x64.
// smem rows padded to 40 bf16 (80B) -> conflict-free quad fragment loads.
// ---------------------------------------------------------------------------
#define GBM 128
#define GBN 128
#define GBK 32
#define LDS_W 40                       // bf16 units per smem row
#define NCHUNK (3 * KDIM / GBK)        // 192

__device__ __forceinline__ void mma16816(float* c, const uint32_t* a, const uint32_t* b)
{
    asm volatile(
        "mma.sync.aligned.m16n8k16.row.col.f32.bf16.bf16.f32 "
        "{%0,%1,%2,%3}, {%4,%5,%6,%7}, {%8,%9}, {%0,%1,%2,%3};"
        : "+f"(c[0]), "+f"(c[1]), "+f"(c[2]), "+f"(c[3])
        : "r"(a[0]), "r"(a[1]), "r"(a[2]), "r"(a[3]), "r"(b[0]), "r"(b[1]));
}

__global__ __launch_bounds__(256) void gemm3_kernel(
    const __nv_bfloat16* __restrict__ Ah, const __nv_bfloat16* __restrict__ Al,
    const __nv_bfloat16* __restrict__ Bh, const __nv_bfloat16* __restrict__ Bl,
    float* __restrict__ C)
{
    __shared__ __nv_bfloat16 sA[2][GBM * LDS_W]; // 2 x 10240 B
    __shared__ __nv_bfloat16 sB[2][GBN * LDS_W];

    const int tid = threadIdx.x;
    const int lane = tid & 31;
    const int wid = tid >> 5;
    const int wm = (wid & 3) * 32;   // warp m offset
    const int wn = (wid >> 2) * 64;  // warp n offset
    const int g = lane >> 2;         // 0..7
    const int t = lane & 3;          // 0..3

    const int bm = blockIdx.y * GBM;
    const int bn = blockIdx.x * GBN;

    // global load mapping: row = tid>>1, col base = (tid&1)*16
    const int lrow = tid >> 1;
    const int lcol = (tid & 1) * 16;

    float acc[2][8][4];
#pragma unroll
    for (int i = 0; i < 2; i++)
#pragma unroll
        for (int j = 0; j < 8; j++)
#pragma unroll
            for (int r = 0; r < 4; r++) acc[i][j][r] = 0.f;

    auto fetch = [&](int c, uint4& ra0, uint4& ra1, uint4& rb0, uint4& rb1) {
        const int pass = c >> 6;              // 64 chunks per pass
        const int k0 = (c & 63) * GBK;
        const __nv_bfloat16* Ap = (pass == 2) ? Al : Ah;
        const __nv_bfloat16* Bp = (pass == 1) ? Bl : Bh;
        const size_t ga = (size_t)(bm + lrow) * KDIM + k0 + lcol;
        const size_t gb = (size_t)(bn + lrow) * KDIM + k0 + lcol;
        ra0 = *(const uint4*)(Ap + ga);
        ra1 = *(const uint4*)(Ap + ga + 8);
        rb0 = *(const uint4*)(Bp + gb);
        rb1 = *(const uint4*)(Bp + gb + 8);
    };
    auto store = [&](int buf, const uint4& ra0, const uint4& ra1,
                     const uint4& rb0, const uint4& rb1) {
        __nv_bfloat16* pa = &sA[buf][lrow * LDS_W + lcol];
        __nv_bfloat16* pb = &sB[buf][lrow * LDS_W + lcol];
        *(uint4*)pa = ra0;
        *(uint4*)(pa + 8) = ra1;
        *(uint4*)pb = rb0;
        *(uint4*)(pb + 8) = rb1;
    };

    {
        uint4 ra0, ra1, rb0, rb1;
        fetch(0, ra0, ra1, rb0, rb1);
        store(0, ra0, ra1, rb0, rb1);
    }
    __syncthreads();

    for (int c = 0; c < NCHUNK; c++) {
        const int buf = c & 1;
        const bool more = (c + 1 < NCHUNK);
        uint4 ra0, ra1, rb0, rb1;
        if (more) fetch(c + 1, ra0, ra1, rb0, rb1);

#pragma unroll
        for (int kk = 0; kk < GBK; kk += 16) {
            uint32_t af[2][4];
#pragma unroll
            for (int mt = 0; mt < 2; mt++) {
                const __nv_bfloat16* base = &sA[buf][(wm + mt * 16 + g) * LDS_W + kk + 2 * t];
                af[mt][0] = *(const uint32_t*)base;
                af[mt][1] = *(const uint32_t*)(base + 8 * LDS_W);
                af[mt][2] = *(const uint32_t*)(base + 8);
                af[mt][3] = *(const uint32_t*)(base + 8 * LDS_W + 8);
            }
            uint32_t bfr[8][2];
#pragma unroll
            for (int nt = 0; nt < 8; nt++) {
                const __nv_bfloat16* base = &sB[buf][(wn + nt * 8 + g) * LDS_W + kk + 2 * t];
                bfr[nt][0] = *(const uint32_t*)base;
                bfr[nt][1] = *(const uint32_t*)(base + 8);
            }
#pragma unroll
            for (int mt = 0; mt < 2; mt++)
#pragma unroll
                for (int nt = 0; nt < 8; nt++)
                    mma16816(acc[mt][nt], af[mt], bfr[nt]);
        }

        if (more) store(buf ^ 1, ra0, ra1, rb0, rb1);
        __syncthreads();
    }

    // Epilogue: c0,c1 = (row g, cols 2t,2t+1); c2,c3 = (row g+8)
#pragma unroll
    for (int mt = 0; mt < 2; mt++) {
        const int r0 = bm + wm + mt * 16 + g;
#pragma unroll
        for (int nt = 0; nt < 8; nt++) {
            const int col = bn + wn + nt * 8 + 2 * t;
            float2 lo = make_float2(acc[mt][nt][0], acc[mt][nt][1]);
            float2 hi = make_float2(acc[mt][nt][2], acc[mt][nt][3]);
            *(float2*)&C[(size_t)r0 * HIDDEN + col] = lo;
            *(float2*)&C[(size_t)(r0 + 8) * HIDDEN + col] = hi;
        }
    }
}

// ---------------------------------------------------------------------------
// RoPE applied in-place to Q and K. One thread per (row, head, pair).
// ---------------------------------------------------------------------------
__global__ void rope_kernel(float* __restrict__ q, float* __restrict__ k)
{
    int idx = blockIdx.x * blockDim.x + threadIdx.x;
    int d = idx & 63;
    int m = idx >> 10;
    int l = m & (SEQL - 1);
    int h = (idx >> 6) & (HEADS - 1);

    float e = (2.0f * (float)d) / 128.0f;
    float inv = 1.0f / powf(10000.0f, e);
    float ang = (float)l * inv;
    float s, c;
    sincosf(ang, &s, &c);

    size_t base = (size_t)m * HIDDEN + h * HD + d;
    float q1 = q[base], q2 = q[base + 64];
    q[base]      = q1 * c - q2 * s;
    q[base + 64] = q2 * c + q1 * s;
    float k1 = k[base], k2 = k[base + 64];
    k[base]      = k1 * c - k2 * s;
    k[base + 64] = k2 * c + k1 * s;
}

// ---------------------------------------------------------------------------
// Flash attention (causal), fp32. Grid: (qtile=32, head=16, batch=2).
// ---------------------------------------------------------------------------
#define LDT 129
#define LDP 65

__global__ __launch_bounds__(256) void flash_kernel(
    const float* __restrict__ Q, const float* __restrict__ K,
    const float* __restrict__ V, float* __restrict__ O)
{
    extern __shared__ float sm[];
    float* Qs = sm;                   // [64][129]
    float* Ks = Qs + 64 * LDT;        // [64][129]
    float* Vs = Ks + 64 * LDT;        // [64][129]
    float* Ps = Vs + 64 * LDT;        // [64][65]

    const int qt = blockIdx.x, h = blockIdx.y, b = blockIdx.z;
    const int tid = threadIdx.x;
    const int ty = tid >> 4, tx = tid & 15;
    const float scale = 0.0883883476483184f; // 1/sqrt(128)

    for (int i = tid; i < 64 * 32; i += 256) {
        int r = i >> 5, c4 = (i & 31) << 2;
        float4 v4 = *(const float4*)&Q[(size_t)(b * SEQL + qt * 64 + r) * HIDDEN + h * HD + c4];
        Qs[r * LDT + c4 + 0] = v4.x;
        Qs[r * LDT + c4 + 1] = v4.y;
        Qs[r * LDT + c4 + 2] = v4.z;
        Qs[r * LDT + c4 + 3] = v4.w;
    }

    float m_i[4], l_i[4], acc[4][8];
#pragma unroll
    for (int i = 0; i < 4; i++) {
        m_i[i] = -INFINITY;
        l_i[i] = 0.f;
#pragma unroll
        for (int j = 0; j < 8; j++) acc[i][j] = 0.f;
    }

    for (int kt = 0; kt <= qt; kt++) {
        __syncthreads();
        for (int i = tid; i < 64 * 32; i += 256) {
            int r = i >> 5, c4 = (i & 31) << 2;
            size_t g = (size_t)(b * SEQL + kt * 64 + r) * HIDDEN + h * HD + c4;
            float4 kv = *(const float4*)&K[g];
            float4 vv = *(const float4*)&V[g];
            Ks[r * LDT + c4 + 0] = kv.x;
            Ks[r * LDT + c4 + 1] = kv.y;
            Ks[r * LDT + c4 + 2] = kv.z;
            Ks[r * LDT + c4 + 3] = kv.w;
            Vs[r * LDT + c4 + 0] = vv.x;
            Vs[r * LDT + c4 + 1] = vv.y;
            Vs[r * LDT + c4 + 2] = vv.z;
            Vs[r * LDT + c4 + 3] = vv.w;
        }
        __syncthreads();

        float s[4][4];
#pragma unroll
        for (int i = 0; i < 4; i++)
#pragma unroll
            for (int j = 0; j < 4; j++) s[i][j] = 0.f;

        for (int kk = 0; kk < HD; kk++) {
            float qa[4], kb[4];
#pragma unroll
            for (int i = 0; i < 4; i++) qa[i] = Qs[(ty * 4 + i) * LDT + kk];
#pragma unroll
            for (int j = 0; j < 4; j++) kb[j] = Ks[(tx * 4 + j) * LDT + kk];
#pragma unroll
            for (int i = 0; i < 4; i++)
#pragma unroll
                for (int j = 0; j < 4; j++)
                    s[i][j] += qa[i] * kb[j];
        }

        const bool diag = (kt == qt);
        float mt[4];
#pragma unroll
        for (int i = 0; i < 4; i++) {
#pragma unroll
            for (int j = 0; j < 4; j++) {
                s[i][j] *= scale;
                if (diag && (tx * 4 + j) > (ty * 4 + i)) s[i][j] = -INFINITY;
            }
            float mm = fmaxf(fmaxf(s[i][0], s[i][1]), fmaxf(s[i][2], s[i][3]));
#pragma unroll
            for (int msk = 1; msk <= 8; msk <<= 1)
                mm = fmaxf(mm, __shfl_xor_sync(0xffffffffu, mm, msk));
            mt[i] = mm;
        }

#pragma unroll
        for (int i = 0; i < 4; i++) {
            float mnew = fmaxf(m_i[i], mt[i]);
            float alpha = expf(m_i[i] - mnew);
            m_i[i] = mnew;
            float ps = 0.f;
#pragma unroll
            for (int j = 0; j < 4; j++) {
                float p = expf(s[i][j] - mnew);
                s[i][j] = p;
                ps += p;
            }
#pragma unroll
            for (int msk = 1; msk <= 8; msk <<= 1)
                ps += __shfl_xor_sync(0xffffffffu, ps, msk);
            l_i[i] = alpha * l_i[i] + ps;
#pragma unroll
            for (int j = 0; j < 8; j++) acc[i][j] *= alpha;
        }

#pragma unroll
        for (int i = 0; i < 4; i++)
#pragma unroll
            for (int j = 0; j < 4; j++)
                Ps[(ty * 4 + i) * LDP + tx * 4 + j] = s[i][j];
        __syncthreads();

        for (int j = 0; j < 64; j++) {
            float pv[4];
#pragma unroll
            for (int i = 0; i < 4; i++) pv[i] = Ps[(ty * 4 + i) * LDP + j];
            float va[8];
#pragma unroll
            for (int c = 0; c < 4; c++) {
                va[c]     = Vs[j * LDT + tx * 4 + c];
                va[4 + c] = Vs[j * LDT + 64 + tx * 4 + c];
            }
#pragma unroll
            for (int i = 0; i < 4; i++)
#pragma unroll
                for (int c = 0; c < 8; c++)
                    acc[i][c] += pv[i] * va[c];
        }
    }

#pragma unroll
    for (int i = 0; i < 4; i++) {
        float inv = 1.0f / l_i[i];
        int r = qt * 64 + ty * 4 + i;
        size_t base = (size_t)(b * SEQL + r) * HIDDEN + h * HD;
#pragma unroll
        for (int c = 0; c < 4; c++) {
            O[base + tx * 4 + c]      = acc[i][c] * inv;
            O[base + 64 + tx * 4 + c] = acc[i][4 + c] * inv;
        }
    }
}

// ---------------------------------------------------------------------------
extern "C" void kernel_launch(void* const* d_in, const int* in_sizes, int n_in,
                              void* d_out, int out_size)
{
    const float* x  = (const float*)d_in[0];
    const float* wq = (const float*)d_in[1];
    const float* wk = (const float*)d_in[2];
    const float* wv = (const float*)d_in[3];
    const float* wo = (const float*)d_in[4];
    float* out = (float*)d_out;

    float *q, *k, *v, *o;
    cudaGetSymbolAddress((void**)&q, g_q);
    cudaGetSymbolAddress((void**)&k, g_k);
    cudaGetSymbolAddress((void**)&v, g_v);
    cudaGetSymbolAddress((void**)&o, g_o);

    __nv_bfloat16 *xh, *xl, *oh, *ol;
    __nv_bfloat16 *wqh, *wql, *wkh, *wkl, *wvh, *wvl, *woh, *wol;
    cudaGetSymbolAddress((void**)&xh, g_xh);
    cudaGetSymbolAddress((void**)&xl, g_xl);
    cudaGetSymbolAddress((void**)&oh, g_oh);
    cudaGetSymbolAddress((void**)&ol, g_ol);
    cudaGetSymbolAddress((void**)&wqh, g_wqh);
    cudaGetSymbolAddress((void**)&wql, g_wql);
    cudaGetSymbolAddress((void**)&wkh, g_wkh);
    cudaGetSymbolAddress((void**)&wkl, g_wkl);
    cudaGetSymbolAddress((void**)&wvh, g_wvh);
    cudaGetSymbolAddress((void**)&wvl, g_wvl);
    cudaGetSymbolAddress((void**)&woh, g_woh);
    cudaGetSymbolAddress((void**)&wol, g_wol);

    const int nx4 = MROWS * HIDDEN / 4;
    const int nw4 = HIDDEN * HIDDEN / 4;
    split_kernel<<<(nx4 + 255) / 256, 256>>>((const float4*)x, xh, xl, nx4);
    split_kernel<<<(nw4 + 255) / 256, 256>>>((const float4*)wq, wqh, wql, nw4);
    split_kernel<<<(nw4 + 255) / 256, 256>>>((const float4*)wk, wkh, wkl, nw4);
    split_kernel<<<(nw4 + 255) / 256, 256>>>((const float4*)wv, wvh, wvl, nw4);
    split_kernel<<<(nw4 + 255) / 256, 256>>>((const float4*)wo, woh, wol, nw4);

    dim3 gg(HIDDEN / GBN, MROWS / GBM); // (16, 32)
    gemm3_kernel<<<gg, 256>>>(xh, xl, wqh, wql, q);
    gemm3_kernel<<<gg, 256>>>(xh, xl, wkh, wkl, k);
    gemm3_kernel<<<gg, 256>>>(xh, xl, wvh, wvl, v);

    rope_kernel<<<(MROWS * HEADS * 64) / 256, 256>>>(q, k);

    int smem = (3 * 64 * LDT + 64 * LDP) * (int)sizeof(float);
    cudaFuncSetAttribute(flash_kernel, cudaFuncAttributeMaxDynamicSharedMemorySize, smem);
    flash_kernel<<<dim3(SEQL / 64, HEADS, NBATCH), 256, smem>>>(q, k, v, o);

    split_kernel<<<(nx4 + 255) / 256, 256>>>((const float4*)o, oh, ol, nx4);
    gemm3_kernel<<<gg, 256>>>(oh, ol, woh, wol, out);
}

// round 4
// speedup vs baseline: 1.9738x; 1.4503x over previous
#include <cuda_runtime.h>
#include <cuda_bf16.h>
#include <math.h>
#include <stdint.h>

#define HIDDEN 2048
#define HEADS 16
#define HD 128
#define SEQL 2048
#define NBATCH 2
#define MROWS (NBATCH * SEQL) // 4096
#define KDIM 2048

// ---------------------------------------------------------------------------
// Scratch: __device__ globals (no cudaMalloc allowed)
// ---------------------------------------------------------------------------
__device__ float g_q[(size_t)MROWS * HIDDEN];
__device__ float g_k[(size_t)MROWS * HIDDEN];
__device__ float g_v[(size_t)MROWS * HIDDEN];
__device__ float g_o[(size_t)MROWS * HIDDEN];

__device__ __nv_bfloat16 g_xh[(size_t)MROWS * HIDDEN];
__device__ __nv_bfloat16 g_xl[(size_t)MROWS * HIDDEN];
__device__ __nv_bfloat16 g_oh[(size_t)MROWS * HIDDEN];
__device__ __nv_bfloat16 g_ol[(size_t)MROWS * HIDDEN];
__device__ __nv_bfloat16 g_wqh[(size_t)HIDDEN * HIDDEN];
__device__ __nv_bfloat16 g_wql[(size_t)HIDDEN * HIDDEN];
__device__ __nv_bfloat16 g_wkh[(size_t)HIDDEN * HIDDEN];
__device__ __nv_bfloat16 g_wkl[(size_t)HIDDEN * HIDDEN];
__device__ __nv_bfloat16 g_wvh[(size_t)HIDDEN * HIDDEN];
__device__ __nv_bfloat16 g_wvl[(size_t)HIDDEN * HIDDEN];
__device__ __nv_bfloat16 g_woh[(size_t)HIDDEN * HIDDEN];
__device__ __nv_bfloat16 g_wol[(size_t)HIDDEN * HIDDEN];

// bf16 split Q/K (post-RoPE) and transposed V for flash
__device__ __nv_bfloat16 g_qh[(size_t)MROWS * HIDDEN];
__device__ __nv_bfloat16 g_ql[(size_t)MROWS * HIDDEN];
__device__ __nv_bfloat16 g_kh[(size_t)MROWS * HIDDEN];
__device__ __nv_bfloat16 g_kl[(size_t)MROWS * HIDDEN];
__device__ __nv_bfloat16 g_vth[(size_t)MROWS * HIDDEN];
__device__ __nv_bfloat16 g_vtl[(size_t)MROWS * HIDDEN];

// ---------------------------------------------------------------------------
// Split fp32 -> (bf16 hi, bf16 lo) elementwise, vectorized x4
// ---------------------------------------------------------------------------
__global__ void split_kernel(const float4* __restrict__ a,
                             __nv_bfloat16* __restrict__ hi,
                             __nv_bfloat16* __restrict__ lo, int n4)
{
    int i = blockIdx.x * blockDim.x + threadIdx.x;
    if (i >= n4) return;
    float4 v = a[i];
    __nv_bfloat16 h0 = __float2bfloat16(v.x);
    __nv_bfloat16 h1 = __float2bfloat16(v.y);
    __nv_bfloat16 h2 = __float2bfloat16(v.z);
    __nv_bfloat16 h3 = __float2bfloat16(v.w);
    __nv_bfloat16 l0 = __float2bfloat16(v.x - __bfloat162float(h0));
    __nv_bfloat16 l1 = __float2bfloat16(v.y - __bfloat162float(h1));
    __nv_bfloat16 l2 = __float2bfloat16(v.z - __bfloat162float(h2));
    __nv_bfloat16 l3 = __float2bfloat16(v.w - __bfloat162float(h3));
    ushort4 hv, lv;
    hv.x = __bfloat16_as_ushort(h0); hv.y = __bfloat16_as_ushort(h1);
    hv.z = __bfloat16_as_ushort(h2); hv.w = __bfloat16_as_ushort(h3);
    lv.x = __bfloat16_as_ushort(l0); lv.y = __bfloat16_as_ushort(l1);
    lv.z = __bfloat16_as_ushort(l2); lv.w = __bfloat16_as_ushort(l3);
    *(ushort4*)(hi + (size_t)i * 4) = hv;
    *(ushort4*)(lo + (size_t)i * 4) = lv;
}

// ---------------------------------------------------------------------------
// bf16x3 GEMM via mma.sync.m16n8k16 (validated R3)
// ---------------------------------------------------------------------------
#define GBM 128
#define GBN 128
#define GBK 32
#define LDS_W 40
#define NCHUNK (3 * KDIM / GBK) // 192

__device__ __forceinline__ void mma16816(float* c, const uint32_t* a, const uint32_t* b)
{
    asm volatile(
        "mma.sync.aligned.m16n8k16.row.col.f32.bf16.bf16.f32 "
        "{%0,%1,%2,%3}, {%4,%5,%6,%7}, {%8,%9}, {%0,%1,%2,%3};"
        : "+f"(c[0]), "+f"(c[1]), "+f"(c[2]), "+f"(c[3])
        : "r"(a[0]), "r"(a[1]), "r"(a[2]), "r"(a[3]), "r"(b[0]), "r"(b[1]));
}

__global__ __launch_bounds__(256) void gemm3_kernel(
    const __nv_bfloat16* __restrict__ Ah, const __nv_bfloat16* __restrict__ Al,
    const __nv_bfloat16* __restrict__ Bh, const __nv_bfloat16* __restrict__ Bl,
    float* __restrict__ C)
{
    __shared__ __nv_bfloat16 sA[2][GBM * LDS_W];
    __shared__ __nv_bfloat16 sB[2][GBN * LDS_W];

    const int tid = threadIdx.x;
    const int lane = tid & 31;
    const int wid = tid >> 5;
    const int wm = (wid & 3) * 32;
    const int wn = (wid >> 2) * 64;
    const int g = lane >> 2;
    const int t = lane & 3;

    const int bm = blockIdx.y * GBM;
    const int bn = blockIdx.x * GBN;

    const int lrow = tid >> 1;
    const int lcol = (tid & 1) * 16;

    float acc[2][8][4];
#pragma unroll
    for (int i = 0; i < 2; i++)
#pragma unroll
        for (int j = 0; j < 8; j++)
#pragma unroll
            for (int r = 0; r < 4; r++) acc[i][j][r] = 0.f;

    auto fetch = [&](int c, uint4& ra0, uint4& ra1, uint4& rb0, uint4& rb1) {
        const int pass = c >> 6;
        const int k0 = (c & 63) * GBK;
        const __nv_bfloat16* Ap = (pass == 2) ? Al : Ah;
        const __nv_bfloat16* Bp = (pass == 1) ? Bl : Bh;
        const size_t ga = (size_t)(bm + lrow) * KDIM + k0 + lcol;
        const size_t gb = (size_t)(bn + lrow) * KDIM + k0 + lcol;
        ra0 = *(const uint4*)(Ap + ga);
        ra1 = *(const uint4*)(Ap + ga + 8);
        rb0 = *(const uint4*)(Bp + gb);
        rb1 = *(const uint4*)(Bp + gb + 8);
    };
    auto store = [&](int buf, const uint4& ra0, const uint4& ra1,
                     const uint4& rb0, const uint4& rb1) {
        __nv_bfloat16* pa = &sA[buf][lrow * LDS_W + lcol];
        __nv_bfloat16* pb = &sB[buf][lrow * LDS_W + lcol];
        *(uint4*)pa = ra0;
        *(uint4*)(pa + 8) = ra1;
        *(uint4*)pb = rb0;
        *(uint4*)(pb + 8) = rb1;
    };

    {
        uint4 ra0, ra1, rb0, rb1;
        fetch(0, ra0, ra1, rb0, rb1);
        store(0, ra0, ra1, rb0, rb1);
    }
    __syncthreads();

    for (int c = 0; c < NCHUNK; c++) {
        const int buf = c & 1;
        const bool more = (c + 1 < NCHUNK);
        uint4 ra0, ra1, rb0, rb1;
        if (more) fetch(c + 1, ra0, ra1, rb0, rb1);

#pragma unroll
        for (int kk = 0; kk < GBK; kk += 16) {
            uint32_t af[2][4];
#pragma unroll
            for (int mt = 0; mt < 2; mt++) {
                const __nv_bfloat16* base = &sA[buf][(wm + mt * 16 + g) * LDS_W + kk + 2 * t];
                af[mt][0] = *(const uint32_t*)base;
                af[mt][1] = *(const uint32_t*)(base + 8 * LDS_W);
                af[mt][2] = *(const uint32_t*)(base + 8);
                af[mt][3] = *(const uint32_t*)(base + 8 * LDS_W + 8);
            }
            uint32_t bfr[8][2];
#pragma unroll
            for (int nt = 0; nt < 8; nt++) {
                const __nv_bfloat16* base = &sB[buf][(wn + nt * 8 + g) * LDS_W + kk + 2 * t];
                bfr[nt][0] = *(const uint32_t*)base;
                bfr[nt][1] = *(const uint32_t*)(base + 8);
            }
#pragma unroll
            for (int mt = 0; mt < 2; mt++)
#pragma unroll
                for (int nt = 0; nt < 8; nt++)
                    mma16816(acc[mt][nt], af[mt], bfr[nt]);
        }

        if (more) store(buf ^ 1, ra0, ra1, rb0, rb1);
        __syncthreads();
    }

#pragma unroll
    for (int mt = 0; mt < 2; mt++) {
        const int r0 = bm + wm + mt * 16 + g;
#pragma unroll
        for (int nt = 0; nt < 8; nt++) {
            const int col = bn + wn + nt * 8 + 2 * t;
            float2 lo = make_float2(acc[mt][nt][0], acc[mt][nt][1]);
            float2 hi = make_float2(acc[mt][nt][2], acc[mt][nt][3]);
            *(float2*)&C[(size_t)r0 * HIDDEN + col] = lo;
            *(float2*)&C[(size_t)(r0 + 8) * HIDDEN + col] = hi;
        }
    }
}

// ---------------------------------------------------------------------------
// RoPE + split to bf16 hi/lo for Q and K.
// One thread per (row, head, pair d in [0,64)).
// ---------------------------------------------------------------------------
__global__ void rope_split_kernel(const float* __restrict__ q, const float* __restrict__ k,
                                  __nv_bfloat16* __restrict__ qh, __nv_bfloat16* __restrict__ ql,
                                  __nv_bfloat16* __restrict__ kh, __nv_bfloat16* __restrict__ kl)
{
    int idx = blockIdx.x * blockDim.x + threadIdx.x;
    int d = idx & 63;
    int m = idx >> 10;
    int l = m & (SEQL - 1);
    int h = (idx >> 6) & (HEADS - 1);

    float e = (2.0f * (float)d) / 128.0f;
    float inv = 1.0f / powf(10000.0f, e);
    float ang = (float)l * inv;
    float s, c;
    sincosf(ang, &s, &c);

    size_t base = (size_t)m * HIDDEN + h * HD + d;
    float q1 = q[base], q2 = q[base + 64];
    float k1 = k[base], k2 = k[base + 64];
    float qa = q1 * c - q2 * s;
    float qb = q2 * c + q1 * s;
    float ka = k1 * c - k2 * s;
    float kb = k2 * c + k1 * s;

    __nv_bfloat16 t0;
    t0 = __float2bfloat16(qa); qh[base] = t0;      ql[base] = __float2bfloat16(qa - __bfloat162float(t0));
    t0 = __float2bfloat16(qb); qh[base + 64] = t0; ql[base + 64] = __float2bfloat16(qb - __bfloat162float(t0));
    t0 = __float2bfloat16(ka); kh[base] = t0;      kl[base] = __float2bfloat16(ka - __bfloat162float(t0));
    t0 = __float2bfloat16(kb); kh[base + 64] = t0; kl[base + 64] = __float2bfloat16(kb - __bfloat162float(t0));
}

// ---------------------------------------------------------------------------
// V transpose + split: v[b*L][h*128+d] -> vt[((b*16+h)*128+d)*2048 + l] bf16 hi/lo
// 32x32 smem tiles. Block (32,8). Grid (L/32, HD/32, 32 bh).
// ---------------------------------------------------------------------------
__global__ __launch_bounds__(256) void vt_split_kernel(
    const float* __restrict__ v,
    __nv_bfloat16* __restrict__ vth, __nv_bfloat16* __restrict__ vtl)
{
    __shared__ float tile[32][33];
    const int bh = blockIdx.z;
    const int b = bh >> 4, h = bh & 15;
    const int l0 = blockIdx.x * 32, d0 = blockIdx.y * 32;
    const int tx = threadIdx.x, ty = threadIdx.y;

#pragma unroll
    for (int i = 0; i < 4; i++) {
        int r = ty + i * 8; // l local
        tile[r][tx] = v[(size_t)(b * SEQL + l0 + r) * HIDDEN + h * HD + d0 + tx];
    }
    __syncthreads();
#pragma unroll
    for (int i = 0; i < 4; i++) {
        int r = ty + i * 8; // d local
        float f = tile[tx][r];
        __nv_bfloat16 hi = __float2bfloat16(f);
        size_t o = ((size_t)((b * HEADS + h) * HD + d0 + r)) * SEQL + l0 + tx;
        vth[o] = hi;
        vtl[o] = __float2bfloat16(f - __bfloat162float(hi));
    }
}

// ---------------------------------------------------------------------------
// Flash attention on tensor cores, bf16 3-term splits throughout.
// CTA: 128 q-rows, 8 warps (warp = 16 rows), K/V tiles of 64 cols.
// Grid: (SEQL/128=16, HEADS, NBATCH).
// ---------------------------------------------------------------------------
#define QW 136   // bf16 per padded row (128 + 8) for Q/K tiles
#define VW 72    // bf16 per padded row (64 + 8) for V^T tiles
// smem offsets in bf16 units
#define OQH 0
#define OQL 17408
#define OKH 34816
#define OKL 43520
#define OVH 52224
#define OVL 61440
#define FLASH_SMEM (70656 * 2) // bytes = 141312

__device__ __forceinline__ void pack_pair(float a, float b, uint32_t& hi_pack, uint32_t& lo_pack)
{
    uint32_t ph;
    asm("cvt.rn.bf16x2.f32 %0, %1, %2;" : "=r"(ph) : "f"(b), "f"(a)); // lo=a, hi=b
    float ra = a - __uint_as_float(ph << 16);
    float rb = b - __uint_as_float(ph & 0xffff0000u);
    asm("cvt.rn.bf16x2.f32 %0, %1, %2;" : "=r"(lo_pack) : "f"(rb), "f"(ra));
    hi_pack = ph;
}

__global__ __launch_bounds__(256) void flash_mma_kernel(
    const __nv_bfloat16* __restrict__ Qh, const __nv_bfloat16* __restrict__ Ql,
    const __nv_bfloat16* __restrict__ Kh, const __nv_bfloat16* __restrict__ Kl,
    const __nv_bfloat16* __restrict__ Vth, const __nv_bfloat16* __restrict__ Vtl,
    float* __restrict__ O)
{
    extern __shared__ __nv_bfloat16 fs[];
    __nv_bfloat16* sQh = fs + OQH;
    __nv_bfloat16* sQl = fs + OQL;
    __nv_bfloat16* sKh = fs + OKH;
    __nv_bfloat16* sKl = fs + OKL;
    __nv_bfloat16* sVh = fs + OVH;
    __nv_bfloat16* sVl = fs + OVL;

    const int qt = blockIdx.x, h = blockIdx.y, b = blockIdx.z;
    const int tid = threadIdx.x, lane = tid & 31, wid = tid >> 5;
    const int g = lane >> 2, t = lane & 3;
    const int wm = wid * 16;
    const float scale = 0.0883883476483184f; // 1/sqrt(128)

    // Load Q tiles (128 rows x 128 bf16, hi & lo)
    {
        const size_t base = (size_t)(b * SEQL + qt * 128) * HIDDEN + h * HD;
#pragma unroll
        for (int it = 0; it < 8; it++) {
            int id = tid + it * 256;
            int r = id >> 4, c8 = (id & 15) * 8;
            *(uint4*)&sQh[r * QW + c8] = *(const uint4*)&Qh[base + (size_t)r * HIDDEN + c8];
            *(uint4*)&sQl[r * QW + c8] = *(const uint4*)&Ql[base + (size_t)r * HIDDEN + c8];
        }
    }

    float m0 = -1e30f, m1 = -1e30f, l0 = 0.f, l1 = 0.f;
    float oacc[16][4];
#pragma unroll
    for (int nt = 0; nt < 16; nt++)
#pragma unroll
        for (int r = 0; r < 4; r++) oacc[nt][r] = 0.f;

    const int nkt = 2 * qt + 2;
    for (int kt = 0; kt < nkt; kt++) {
        __syncthreads();
        // Load K (64x128) and V^T (128x64) hi/lo tiles
#pragma unroll
        for (int it = 0; it < 4; it++) {
            int id = tid + it * 256;
            int r = id >> 4, c8 = (id & 15) * 8;
            size_t gk = (size_t)(b * SEQL + kt * 64 + r) * HIDDEN + h * HD + c8;
            *(uint4*)&sKh[r * QW + c8] = *(const uint4*)&Kh[gk];
            *(uint4*)&sKl[r * QW + c8] = *(const uint4*)&Kl[gk];
            int rv = id >> 3, cv = (id & 7) * 8;
            size_t gv = (size_t)((b * HEADS + h) * HD + rv) * SEQL + kt * 64 + cv;
            *(uint4*)&sVh[rv * VW + cv] = *(const uint4*)&Vth[gv];
            *(uint4*)&sVl[rv * VW + cv] = *(const uint4*)&Vtl[gv];
        }
        __syncthreads();

        // S = Qh Kh + Qh Kl + Ql Kh
        float sacc[8][4];
#pragma unroll
        for (int nt = 0; nt < 8; nt++)
#pragma unroll
            for (int r = 0; r < 4; r++) sacc[nt][r] = 0.f;

#pragma unroll
        for (int kc = 0; kc < 8; kc++) {
            const int kk = kc * 16;
            uint32_t aqh[4], aql[4];
            const __nv_bfloat16* ah = &sQh[(wm + g) * QW + kk + 2 * t];
            aqh[0] = *(const uint32_t*)ah;
            aqh[1] = *(const uint32_t*)(ah + 8 * QW);
            aqh[2] = *(const uint32_t*)(ah + 8);
            aqh[3] = *(const uint32_t*)(ah + 8 * QW + 8);
            const __nv_bfloat16* al = &sQl[(wm + g) * QW + kk + 2 * t];
            aql[0] = *(const uint32_t*)al;
            aql[1] = *(const uint32_t*)(al + 8 * QW);
            aql[2] = *(const uint32_t*)(al + 8);
            aql[3] = *(const uint32_t*)(al + 8 * QW + 8);
#pragma unroll
            for (int nt = 0; nt < 8; nt++) {
                const __nv_bfloat16* bh = &sKh[(nt * 8 + g) * QW + kk + 2 * t];
                uint32_t bhf[2] = { *(const uint32_t*)bh, *(const uint32_t*)(bh + 8) };
                const __nv_bfloat16* bl = &sKl[(nt * 8 + g) * QW + kk + 2 * t];
                uint32_t blf[2] = { *(const uint32_t*)bl, *(const uint32_t*)(bl + 8) };
                mma16816(sacc[nt], aqh, bhf);
                mma16816(sacc[nt], aqh, blf);
                mma16816(sacc[nt], aql, bhf);
            }
        }

        // scale + causal mask
        const int row0 = qt * 128 + wm + g;
        const int row1 = row0 + 8;
#pragma unroll
        for (int nt = 0; nt < 8; nt++) {
            sacc[nt][0] *= scale; sacc[nt][1] *= scale;
            sacc[nt][2] *= scale; sacc[nt][3] *= scale;
        }
        if (kt * 64 + 63 > qt * 128 + wm) {
#pragma unroll
            for (int nt = 0; nt < 8; nt++) {
                const int col = kt * 64 + nt * 8 + 2 * t;
                if (col > row0)     sacc[nt][0] = -1e30f;
                if (col + 1 > row0) sacc[nt][1] = -1e30f;
                if (col > row1)     sacc[nt][2] = -1e30f;
                if (col + 1 > row1) sacc[nt][3] = -1e30f;
            }
        }

        // online softmax (rows g and g+8), quad shuffle reductions
        float mt0 = -1e30f, mt1 = -1e30f;
#pragma unroll
        for (int nt = 0; nt < 8; nt++) {
            mt0 = fmaxf(mt0, fmaxf(sacc[nt][0], sacc[nt][1]));
            mt1 = fmaxf(mt1, fmaxf(sacc[nt][2], sacc[nt][3]));
        }
        mt0 = fmaxf(mt0, __shfl_xor_sync(0xffffffffu, mt0, 1));
        mt0 = fmaxf(mt0, __shfl_xor_sync(0xffffffffu, mt0, 2));
        mt1 = fmaxf(mt1, __shfl_xor_sync(0xffffffffu, mt1, 1));
        mt1 = fmaxf(mt1, __shfl_xor_sync(0xffffffffu, mt1, 2));

        const float nm0 = fmaxf(m0, mt0), nm1 = fmaxf(m1, mt1);
        const float alpha0 = __expf(m0 - nm0), alpha1 = __expf(m1 - nm1);
        float ps0 = 0.f, ps1 = 0.f;
#pragma unroll
        for (int nt = 0; nt < 8; nt++) {
            sacc[nt][0] = __expf(sacc[nt][0] - nm0);
            sacc[nt][1] = __expf(sacc[nt][1] - nm0);
            sacc[nt][2] = __expf(sacc[nt][2] - nm1);
            sacc[nt][3] = __expf(sacc[nt][3] - nm1);
            ps0 += sacc[nt][0] + sacc[nt][1];
            ps1 += sacc[nt][2] + sacc[nt][3];
        }
        ps0 += __shfl_xor_sync(0xffffffffu, ps0, 1);
        ps0 += __shfl_xor_sync(0xffffffffu, ps0, 2);
        ps1 += __shfl_xor_sync(0xffffffffu, ps1, 1);
        ps1 += __shfl_xor_sync(0xffffffffu, ps1, 2);
        l0 = alpha0 * l0 + ps0; m0 = nm0;
        l1 = alpha1 * l1 + ps1; m1 = nm1;
#pragma unroll
        for (int nt = 0; nt < 16; nt++) {
            oacc[nt][0] *= alpha0; oacc[nt][1] *= alpha0;
            oacc[nt][2] *= alpha1; oacc[nt][3] *= alpha1;
        }

        // repack P fragments (C-frag of S -> A-frag of PV), hi/lo split
        uint32_t ph[4][4], pl[4][4];
#pragma unroll
        for (int kc = 0; kc < 4; kc++) {
            const int j0 = 2 * kc, j1 = 2 * kc + 1;
            pack_pair(sacc[j0][0], sacc[j0][1], ph[kc][0], pl[kc][0]);
            pack_pair(sacc[j0][2], sacc[j0][3], ph[kc][1], pl[kc][1]);
            pack_pair(sacc[j1][0], sacc[j1][1], ph[kc][2], pl[kc][2]);
            pack_pair(sacc[j1][2], sacc[j1][3], ph[kc][3], pl[kc][3]);
        }

        // O += Ph Vh + Ph Vl + Pl Vh
#pragma unroll
        for (int kc = 0; kc < 4; kc++) {
#pragma unroll
            for (int nt = 0; nt < 16; nt++) {
                const __nv_bfloat16* vh = &sVh[(nt * 8 + g) * VW + kc * 16 + 2 * t];
                uint32_t bvh[2] = { *(const uint32_t*)vh, *(const uint32_t*)(vh + 8) };
                const __nv_bfloat16* vl = &sVl[(nt * 8 + g) * VW + kc * 16 + 2 * t];
                uint32_t bvl[2] = { *(const uint32_t*)vl, *(const uint32_t*)(vl + 8) };
                mma16816(oacc[nt], ph[kc], bvh);
                mma16816(oacc[nt], ph[kc], bvl);
                mma16816(oacc[nt], pl[kc], bvh);
            }
        }
    }

    // epilogue
    const float i0 = 1.0f / l0, i1 = 1.0f / l1;
    const size_t rbase = (size_t)(b * SEQL + qt * 128 + wm + g) * HIDDEN + h * HD + 2 * t;
#pragma unroll
    for (int nt = 0; nt < 16; nt++) {
        *(float2*)&O[rbase + nt * 8] = make_float2(oacc[nt][0] * i0, oacc[nt][1] * i0);
        *(float2*)&O[rbase + 8 * HIDDEN + nt * 8] = make_float2(oacc[nt][2] * i1, oacc[nt][3] * i1);
    }
}

// ---------------------------------------------------------------------------
extern "C" void kernel_launch(void* const* d_in, const int* in_sizes, int n_in,
                              void* d_out, int out_size)
{
    const float* x  = (const float*)d_in[0];
    const float* wq = (const float*)d_in[1];
    const float* wk = (const float*)d_in[2];
    const float* wv = (const float*)d_in[3];
    const float* wo = (const float*)d_in[4];
    float* out = (float*)d_out;

    float *q, *k, *v, *o;
    cudaGetSymbolAddress((void**)&q, g_q);
    cudaGetSymbolAddress((void**)&k, g_k);
    cudaGetSymbolAddress((void**)&v, g_v);
    cudaGetSymbolAddress((void**)&o, g_o);

    __nv_bfloat16 *xh, *xl, *oh, *ol;
    __nv_bfloat16 *wqh, *wql, *wkh, *wkl, *wvh, *wvl, *woh, *wol;
    __nv_bfloat16 *qh, *ql, *kh, *kl, *vth, *vtl;
    cudaGetSymbolAddress((void**)&xh, g_xh);
    cudaGetSymbolAddress((void**)&xl, g_xl);
    cudaGetSymbolAddress((void**)&oh, g_oh);
    cudaGetSymbolAddress((void**)&ol, g_ol);
    cudaGetSymbolAddress((void**)&wqh, g_wqh);
    cudaGetSymbolAddress((void**)&wql, g_wql);
    cudaGetSymbolAddress((void**)&wkh, g_wkh);
    cudaGetSymbolAddress((void**)&wkl, g_wkl);
    cudaGetSymbolAddress((void**)&wvh, g_wvh);
    cudaGetSymbolAddress((void**)&wvl, g_wvl);
    cudaGetSymbolAddress((void**)&woh, g_woh);
    cudaGetSymbolAddress((void**)&wol, g_wol);
    cudaGetSymbolAddress((void**)&qh, g_qh);
    cudaGetSymbolAddress((void**)&ql, g_ql);
    cudaGetSymbolAddress((void**)&kh, g_kh);
    cudaGetSymbolAddress((void**)&kl, g_kl);
    cudaGetSymbolAddress((void**)&vth, g_vth);
    cudaGetSymbolAddress((void**)&vtl, g_vtl);

    const int nx4 = MROWS * HIDDEN / 4;
    const int nw4 = HIDDEN * HIDDEN / 4;
    split_kernel<<<(nx4 + 255) / 256, 256>>>((const float4*)x, xh, xl, nx4);
    split_kernel<<<(nw4 + 255) / 256, 256>>>((const float4*)wq, wqh, wql, nw4);
    split_kernel<<<(nw4 + 255) / 256, 256>>>((const float4*)wk, wkh, wkl, nw4);
    split_kernel<<<(nw4 + 255) / 256, 256>>>((const float4*)wv, wvh, wvl, nw4);
    split_kernel<<<(nw4 + 255) / 256, 256>>>((const float4*)wo, woh, wol, nw4);

    dim3 gg(HIDDEN / GBN, MROWS / GBM); // (16, 32)
    gemm3_kernel<<<gg, 256>>>(xh, xl, wqh, wql, q);
    gemm3_kernel<<<gg, 256>>>(xh, xl, wkh, wkl, k);
    gemm3_kernel<<<gg, 256>>>(xh, xl, wvh, wvl, v);

    rope_split_kernel<<<(MROWS * HEADS * 64) / 256, 256>>>(q, k, qh, ql, kh, kl);
    vt_split_kernel<<<dim3(SEQL / 32, HD / 32, NBATCH * HEADS), dim3(32, 8)>>>(v, vth, vtl);

    cudaFuncSetAttribute(flash_mma_kernel, cudaFuncAttributeMaxDynamicSharedMemorySize, FLASH_SMEM);
    flash_mma_kernel<<<dim3(SEQL / 128, HEADS, NBATCH), 256, FLASH_SMEM>>>(
        qh, ql, kh, kl, vth, vtl, o);

    split_kernel<<<(nx4 + 255) / 256, 256>>>((const float4*)o, oh, ol, nx4);
    gemm3_kernel<<<gg, 256>>>(oh, ol, woh, wol, out);
}